// round 5
// baseline (speedup 1.0000x reference)
#include <cuda_runtime.h>
#include <cuda_bf16.h>

// PMF: out[p] = relu(dot(user_emb[user_ids[p]], item_emb[item_ids[p]])), D=64 fp32.
//
// R5: locality restructuring. The user table (256MB) exceeds L2 (126MB), and
// random pair order makes user-row repeats miss L2 (~444MB user DRAM traffic).
// Pipeline: bucket pairs by user_id>>11 (512 buckets, ~512KB of user rows per
// bucket), then process in bucket order so repeats are L2 hits:
//   K0: zero histogram      K1: per-CTA smem histogram -> global
//   K2: exclusive scan (1 block)
//   K3: scatter packed (uid|iid|p) records into bucket order
//   K4: main gather-dot-relu over the bucketed records (R4's flat PB=8 MLP
//       structure), storing to the original index p.
// All scratch in __device__ globals; all launches graph-capturable.
// Fallback to the direct R4 kernel if sizes exceed the packing budget.

#define HIDDEN 64

// ---------------- bucketing config ----------------
#define BUCKETS 512
#define BSHIFT 11                      // bucket = uid >> 11 (1M users -> 489 buckets)
#define CAP (1 << 21)                  // max pairs (2,097,152 >= 2,000,000)
#define AUX_THREADS 256
#define AUX_K 8
#define TILE (AUX_THREADS * AUX_K)     // 2048 pairs per aux CTA

// pack: uid [0,20) | iid [20,37) | p [37,58)
#define UID_BITS 20
#define IID_BITS 17

__device__ int g_hist[BUCKETS];
__device__ int g_offsets[BUCKETS];
__device__ unsigned long long g_pairs[CAP];

// ---------------- K0: zero histogram ----------------
__global__ void zero_kernel() {
    int i = threadIdx.x + blockIdx.x * blockDim.x;
    if (i < BUCKETS) g_hist[i] = 0;
}

// ---------------- K1: histogram ----------------
__global__ __launch_bounds__(AUX_THREADS)
void hist_kernel(const int* __restrict__ user_ids, int n) {
    __shared__ int h[BUCKETS];
    for (int i = threadIdx.x; i < BUCKETS; i += AUX_THREADS) h[i] = 0;
    __syncthreads();
    int base = blockIdx.x * TILE;
    #pragma unroll
    for (int k = 0; k < AUX_K; k++) {
        int i = base + threadIdx.x + k * AUX_THREADS;
        if (i < n) atomicAdd(&h[user_ids[i] >> BSHIFT], 1);
    }
    __syncthreads();
    for (int i = threadIdx.x; i < BUCKETS; i += AUX_THREADS)
        if (h[i]) atomicAdd(&g_hist[i], h[i]);
}

// ---------------- K2: exclusive scan (single block of BUCKETS threads) ----
__global__ __launch_bounds__(BUCKETS)
void scan_kernel() {
    __shared__ int s[BUCKETS];
    int t = threadIdx.x;
    int my = g_hist[t];
    s[t] = my;
    __syncthreads();
    for (int off = 1; off < BUCKETS; off <<= 1) {
        int v = (t >= off) ? s[t - off] : 0;
        __syncthreads();
        s[t] += v;
        __syncthreads();
    }
    g_offsets[t] = s[t] - my;   // exclusive prefix
}

// ---------------- K3: scatter into bucket order ----------------
__global__ __launch_bounds__(AUX_THREADS)
void scatter_kernel(const int* __restrict__ user_ids,
                    const int* __restrict__ item_ids, int n) {
    __shared__ int h[BUCKETS];
    __shared__ int basea[BUCKETS];
    for (int i = threadIdx.x; i < BUCKETS; i += AUX_THREADS) h[i] = 0;
    __syncthreads();

    int base = blockIdx.x * TILE;
    int myb[AUX_K], myl[AUX_K], myu[AUX_K];
    #pragma unroll
    for (int k = 0; k < AUX_K; k++) {
        int i = base + threadIdx.x + k * AUX_THREADS;
        myb[k] = -1;
        if (i < n) {
            int uid = user_ids[i];
            myu[k] = uid;
            int b = uid >> BSHIFT;
            myb[k] = b;
            myl[k] = atomicAdd(&h[b], 1);
        }
    }
    __syncthreads();
    for (int i = threadIdx.x; i < BUCKETS; i += AUX_THREADS)
        basea[i] = h[i] ? atomicAdd(&g_offsets[i], h[i]) : 0;
    __syncthreads();

    #pragma unroll
    for (int k = 0; k < AUX_K; k++) {
        int i = base + threadIdx.x + k * AUX_THREADS;
        if (i < n) {
            int pos = basea[myb[k]] + myl[k];
            unsigned long long rec =
                  (unsigned long long)(unsigned)myu[k]
                | ((unsigned long long)(unsigned)item_ids[i] << UID_BITS)
                | ((unsigned long long)(unsigned)i << (UID_BITS + IID_BITS));
            g_pairs[pos] = rec;
        }
    }
}

// ---------------- K4: main kernel over bucketed records ----------------
#define THREADS 256
#define GROUPS_PER_BLOCK (THREADS / 16)            // 16
#define PB 8
#define PAIRS_PER_BLOCK (GROUPS_PER_BLOCK * PB)     // 128

__global__ __launch_bounds__(THREADS, 3)
void pmf_sorted_kernel(const float* __restrict__ user_emb,
                       const float* __restrict__ item_emb,
                       float*       __restrict__ out,
                       int num_pairs)
{
    const int group = threadIdx.x >> 4;
    const int lane  = threadIdx.x & 15;
    const int base  = blockIdx.x * PAIRS_PER_BLOCK + group;

    // Phase 1: load packed records (broadcast within group), independent.
    unsigned long long rec[PB];
    #pragma unroll
    for (int k = 0; k < PB; k++) {
        int j = base + k * GROUPS_PER_BLOCK;
        int q = (j < num_pairs) ? j : 0;
        rec[k] = __ldg(&g_pairs[q]);
    }

    // Phase 2: all row loads, independent, front-batched (16 LDG.128/thread).
    float4 u[PB], v[PB];
    #pragma unroll
    for (int k = 0; k < PB; k++) {
        int uid = (int)(rec[k] & ((1u << UID_BITS) - 1));
        int iid = (int)((rec[k] >> UID_BITS) & ((1u << IID_BITS) - 1));
        u[k] = __ldg(reinterpret_cast<const float4*>(
                   user_emb + (long long)uid * HIDDEN) + lane);
        v[k] = __ldg(reinterpret_cast<const float4*>(
                   item_emb + (long long)iid * HIDDEN) + lane);
    }

    // Phase 3: dot, 16-lane reduction, store to ORIGINAL index.
    #pragma unroll
    for (int k = 0; k < PB; k++) {
        float acc = u[k].x * v[k].x + u[k].y * v[k].y
                  + u[k].z * v[k].z + u[k].w * v[k].w;
        acc += __shfl_xor_sync(0xFFFFFFFFu, acc, 8);
        acc += __shfl_xor_sync(0xFFFFFFFFu, acc, 4);
        acc += __shfl_xor_sync(0xFFFFFFFFu, acc, 2);
        acc += __shfl_xor_sync(0xFFFFFFFFu, acc, 1);
        int j = base + k * GROUPS_PER_BLOCK;
        if (lane == 0 && j < num_pairs) {
            int p = (int)(rec[k] >> (UID_BITS + IID_BITS));
            out[p] = fmaxf(acc, 0.0f);
        }
    }
}

// ---------------- fallback: direct (R4) ----------------
__global__ __launch_bounds__(THREADS, 3)
void pmf_direct_kernel(const float* __restrict__ user_emb,
                       const float* __restrict__ item_emb,
                       const int*   __restrict__ user_ids,
                       const int*   __restrict__ item_ids,
                       float*       __restrict__ out,
                       int num_pairs)
{
    const int group = threadIdx.x >> 4;
    const int lane  = threadIdx.x & 15;
    const int base  = blockIdx.x * PAIRS_PER_BLOCK + group;

    int uid[PB], iid[PB];
    #pragma unroll
    for (int k = 0; k < PB; k++) {
        int p = base + k * GROUPS_PER_BLOCK;
        int q = (p < num_pairs) ? p : 0;
        uid[k] = __ldg(&user_ids[q]);
        iid[k] = __ldg(&item_ids[q]);
    }
    float4 u[PB], v[PB];
    #pragma unroll
    for (int k = 0; k < PB; k++) {
        u[k] = __ldg(reinterpret_cast<const float4*>(
                   user_emb + (long long)uid[k] * HIDDEN) + lane);
        v[k] = __ldg(reinterpret_cast<const float4*>(
                   item_emb + (long long)iid[k] * HIDDEN) + lane);
    }
    #pragma unroll
    for (int k = 0; k < PB; k++) {
        float acc = u[k].x * v[k].x + u[k].y * v[k].y
                  + u[k].z * v[k].z + u[k].w * v[k].w;
        acc += __shfl_xor_sync(0xFFFFFFFFu, acc, 8);
        acc += __shfl_xor_sync(0xFFFFFFFFu, acc, 4);
        acc += __shfl_xor_sync(0xFFFFFFFFu, acc, 2);
        acc += __shfl_xor_sync(0xFFFFFFFFu, acc, 1);
        int p = base + k * GROUPS_PER_BLOCK;
        if (lane == 0 && p < num_pairs)
            out[p] = fmaxf(acc, 0.0f);
    }
}

extern "C" void kernel_launch(void* const* d_in, const int* in_sizes, int n_in,
                              void* d_out, int out_size)
{
    const float* user_emb = (const float*)d_in[0];
    const float* item_emb = (const float*)d_in[1];
    const int*   user_ids = (const int*)d_in[2];
    const int*   item_ids = (const int*)d_in[3];
    float*       out      = (float*)d_out;

    int num_pairs = in_sizes[2];
    long long num_users = in_sizes[0] / HIDDEN;
    long long num_items = in_sizes[1] / HIDDEN;

    bool can_bucket = (num_pairs <= CAP)
                   && (num_users <= (1LL << UID_BITS))
                   && (num_items <= (1LL << IID_BITS));

    int main_blocks = (num_pairs + PAIRS_PER_BLOCK - 1) / PAIRS_PER_BLOCK;

    if (!can_bucket) {
        pmf_direct_kernel<<<main_blocks, THREADS>>>(
            user_emb, item_emb, user_ids, item_ids, out, num_pairs);
        return;
    }

    int aux_blocks = (num_pairs + TILE - 1) / TILE;

    zero_kernel<<<(BUCKETS + 255) / 256, 256>>>();
    hist_kernel<<<aux_blocks, AUX_THREADS>>>(user_ids, num_pairs);
    scan_kernel<<<1, BUCKETS>>>();
    scatter_kernel<<<aux_blocks, AUX_THREADS>>>(user_ids, item_ids, num_pairs);
    pmf_sorted_kernel<<<main_blocks, THREADS>>>(user_emb, item_emb, out, num_pairs);
}